// round 15
// baseline (speedup 1.0000x reference)
#include <cuda_runtime.h>
#include <cstdint>

typedef unsigned long long u64;

#define TT 14
#define HH 7
#define FF 12
#define NTHR 128

// constant-bank PAIR image (each entry = duplicated float pair):
// [l0 252][l1 448][w1 12][w2 14][blin,b2] = 728 pairs = 5824 B
#define L0OFF 0
#define L1OFF 252
#define W1OFF 700
#define W2OFF 712
#define BOFF  726
#define WTOTAL 728

__device__    u64 g_prep[WTOTAL];
__constant__  u64 c_pr[WTOTAL];

#define HALF2 0x3F0000003F000000ULL   // (0.5f, 0.5f)
#define ONE2  0x3F8000003F800000ULL   // (1.0f, 1.0f)

// ---------- hardware tanh (1 MUFU op) ----------
__device__ __forceinline__ float tanh_(float x) {
    float r;
    asm("tanh.approx.f32 %0, %1;" : "=f"(r) : "f"(x));
    return r;
}

// ---------- packed f32x2 primitives ----------
__device__ __forceinline__ u64 fma2(u64 a, u64 b, u64 c) {
    u64 d;
    asm("fma.rn.f32x2 %0, %1, %2, %3;" : "=l"(d) : "l"(a), "l"(b), "l"(c));
    return d;
}
__device__ __forceinline__ u64 mul2(u64 a, u64 b) {
    u64 d;
    asm("mul.rn.f32x2 %0, %1, %2;" : "=l"(d) : "l"(a), "l"(b));
    return d;
}
__device__ __forceinline__ u64 add2(u64 a, u64 b) {
    u64 d;
    asm("add.rn.f32x2 %0, %1, %2;" : "=l"(d) : "l"(a), "l"(b));
    return d;
}
__device__ __forceinline__ u64 pk2(float lo, float hi) {
    u64 r;
    asm("mov.b64 %0, {%1, %2};" : "=l"(r) : "f"(lo), "f"(hi));
    return r;
}
__device__ __forceinline__ void upk2(u64 v, float& lo, float& hi) {
    asm("mov.b64 {%0, %1}, %2;" : "=f"(lo), "=f"(hi) : "l"(v));
}
__device__ __forceinline__ u64 tanh2p(u64 v) {
    float lo, hi; upk2(v, lo, hi);
    return pk2(tanh_(lo), tanh_(hi));
}
__device__ __forceinline__ float lof(u64 v) {
    float lo, hi; upk2(v, lo, hi);
    return lo;
}

// Gate-folded packed cell update (weights pre-scaled; h carried as h'=2h).
__device__ __forceinline__ u64 cell_update_p(const u64 z[4], u64& c) {
    u64 ti = tanh2p(z[0]);
    u64 tf = tanh2p(z[1]);
    u64 tg = tanh2p(z[2]);
    u64 to = tanh2p(z[3]);
    u64 iv = fma2(ti, HALF2, HALF2);
    u64 fv = fma2(tf, HALF2, HALF2);
    u64 cv = fma2(fv, c, mul2(iv, tg));
    c = cv;
    return mul2(add2(to, ONE2), tanh2p(cv));   // = 2*h_true
}
// Scalar version for light blocks.
__device__ __forceinline__ float cell_update_s(const float z[4], float& c) {
    float ti = tanh_(z[0]);
    float tf = tanh_(z[1]);
    float tg = tanh_(z[2]);
    float to = tanh_(z[3]);
    float iv = fmaf(0.5f, ti, 0.5f);
    float fv = fmaf(0.5f, tf, 0.5f);
    float cv = fmaf(fv, c, iv * tg);
    c = cv;
    return (to + 1.0f) * tanh_(cv);
}

// ---------- prep kernel: scale + layout weights as dup pairs ----------
__device__ __forceinline__ u64 dup_(float w) {
    unsigned b = __float_as_uint(w);
    return ((u64)b << 32) | b;
}
__global__ void prep_weights(
    const float* __restrict__ w1,  const float* __restrict__ b1,
    const float* __restrict__ wih0, const float* __restrict__ whh0,
    const float* __restrict__ bih0, const float* __restrict__ bhh0,
    const float* __restrict__ wih1, const float* __restrict__ whh1,
    const float* __restrict__ bih1, const float* __restrict__ bhh1,
    const float* __restrict__ w2,  const float* __restrict__ b2)
{
    int r = threadIdx.x;
    if (r < 28) {
        int g = r / 7, j = r % 7;
        const bool ifo = (g != 2);
        const float sb = ifo ? 0.5f : 1.0f;     // bias scale
        const float sx = ifo ? 0.5f : 1.0f;     // non-hidden-input weight scale
        const float sh = ifo ? 0.25f : 0.5f;    // hidden-input weight scale

        g_prep[L0OFF + j * 36 + g] = dup_((bih0[r] + bhh0[r]) * sb);
        g_prep[L0OFF + j * 36 + 4 + g * 8 + 0] = dup_(wih0[r] * sx);
#pragma unroll
        for (int k = 0; k < 7; k++)
            g_prep[L0OFF + j * 36 + 4 + g * 8 + 1 + k] = dup_(whh0[r * 7 + k] * sh);

        g_prep[L1OFF + r * 16 + 0] = dup_((bih1[r] + bhh1[r]) * sb);
#pragma unroll
        for (int k = 0; k < 7; k++)
            g_prep[L1OFF + r * 16 + 1 + k] = dup_(wih1[r * 7 + k] * sh);
#pragma unroll
        for (int k = 0; k < 7; k++)
            g_prep[L1OFF + r * 16 + 8 + k] = dup_(whh1[r * 7 + k] * sh);
        g_prep[L1OFF + r * 16 + 15] = 0ull;
    }
    if (r < FF)     g_prep[W1OFF + r] = dup_(w1[r]);
    if (r < 2 * HH) g_prep[W2OFF + r] = dup_(w2[r] * 0.5f);   // undo h' = 2h
    if (r == 0) { g_prep[BOFF + 0] = dup_(b1[0]); g_prep[BOFF + 1] = dup_(b2[0]); }
}

// ---------- shared phase 1: coalesced linear1 + tanh ----------
// half==-1: scalar layout (s_u floats); else write into u64 halves.
__device__ __forceinline__ void phase1(
    const float* __restrict__ x, int base, int cnt, float* uf, bool packed, int tid)
{
    const float blin = lof(c_pr[BOFF + 0]);
    const float* xb = x + (long)base * TT * FF;
    const int iters = (cnt + NTHR - 1) / NTHR;
#pragma unroll 1
    for (int it = 0; it < iters; it++) {
        int idx = it * NTHR + tid;
        if (idx < cnt) {
            int bl = idx / TT;
            int t  = idx - bl * TT;
            const float4* px = (const float4*)(xb + (long)idx * FF);
            float4 a0 = px[0], a1 = px[1], a2 = px[2];
            float s = blin;
            s = fmaf(a0.x, lof(c_pr[W1OFF + 0]), s);
            s = fmaf(a0.y, lof(c_pr[W1OFF + 1]), s);
            s = fmaf(a0.z, lof(c_pr[W1OFF + 2]), s);
            s = fmaf(a0.w, lof(c_pr[W1OFF + 3]), s);
            s = fmaf(a1.x, lof(c_pr[W1OFF + 4]), s);
            s = fmaf(a1.y, lof(c_pr[W1OFF + 5]), s);
            s = fmaf(a1.z, lof(c_pr[W1OFF + 6]), s);
            s = fmaf(a1.w, lof(c_pr[W1OFF + 7]), s);
            s = fmaf(a2.x, lof(c_pr[W1OFF + 8]), s);
            s = fmaf(a2.y, lof(c_pr[W1OFF + 9]), s);
            s = fmaf(a2.z, lof(c_pr[W1OFF + 10]), s);
            s = fmaf(a2.w, lof(c_pr[W1OFF + 11]), s);
            float v = tanh_(s);
            if (packed) uf[(((bl & 127) * 15) + t) * 2 + (bl >> 7)] = v;
            else        uf[bl * 15 + t] = v;
        }
    }
}

// ---------- packed block: 256 elements, 2 per thread in f32x2 ----------
__device__ __forceinline__ void run_packed(
    const float* __restrict__ x, float* __restrict__ out, int B, int base,
    u64* s_up, int tid)
{
    const int nb = min(2 * NTHR, B - base);
    if (nb <= 0) return;
    phase1(x, base, nb * TT, (float*)s_up, true, tid);
    __syncthreads();

    if (tid >= nb) return;
    const bool hasB = (NTHR + tid < nb);

    u64 h0[HH], c0[HH], h1[HH], c1[HH];
#pragma unroll
    for (int j = 0; j < HH; j++) { h0[j] = 0ull; c0[j] = 0ull; h1[j] = 0ull; c1[j] = 0ull; }

#pragma unroll 1
    for (int t = 0; t < TT; t++) {
        const u64 xin = s_up[tid * 15 + t];

        // layer 0
        u64 hn[HH];
#pragma unroll
        for (int j = 0; j < HH; j++) {
            u64 z[4];
#pragma unroll
            for (int g = 0; g < 4; g++) {
                const int wb = L0OFF + j * 36 + 4 + g * 8;
                u64 zz = fma2(xin, c_pr[wb + 0], c_pr[L0OFF + j * 36 + g]);
                zz = fma2(h0[0], c_pr[wb + 1], zz);
                zz = fma2(h0[1], c_pr[wb + 2], zz);
                zz = fma2(h0[2], c_pr[wb + 3], zz);
                zz = fma2(h0[3], c_pr[wb + 4], zz);
                zz = fma2(h0[4], c_pr[wb + 5], zz);
                zz = fma2(h0[5], c_pr[wb + 6], zz);
                zz = fma2(h0[6], c_pr[wb + 7], zz);
                z[g] = zz;
            }
            hn[j] = cell_update_p(z, c0[j]);
        }

        // layer 1
        u64 hn1[HH];
#pragma unroll
        for (int j = 0; j < HH; j++) {
            u64 z[4];
#pragma unroll
            for (int g = 0; g < 4; g++) {
                const int rp = L1OFF + (g * HH + j) * 16;
                u64 zz = c_pr[rp + 0];
                zz = fma2(hn[0], c_pr[rp + 1], zz);
                zz = fma2(hn[1], c_pr[rp + 2], zz);
                zz = fma2(hn[2], c_pr[rp + 3], zz);
                zz = fma2(hn[3], c_pr[rp + 4], zz);
                zz = fma2(hn[4], c_pr[rp + 5], zz);
                zz = fma2(hn[5], c_pr[rp + 6], zz);
                zz = fma2(hn[6], c_pr[rp + 7], zz);
                zz = fma2(h1[0], c_pr[rp + 8], zz);
                zz = fma2(h1[1], c_pr[rp + 9], zz);
                zz = fma2(h1[2], c_pr[rp + 10], zz);
                zz = fma2(h1[3], c_pr[rp + 11], zz);
                zz = fma2(h1[4], c_pr[rp + 12], zz);
                zz = fma2(h1[5], c_pr[rp + 13], zz);
                zz = fma2(h1[6], c_pr[rp + 14], zz);
                z[g] = zz;
            }
            hn1[j] = cell_update_p(z, c1[j]);
        }

#pragma unroll
        for (int j = 0; j < HH; j++) { h0[j] = hn[j]; h1[j] = hn1[j]; }
    }

    // phase 3 (w2 pairs pre-scaled by 0.5 to undo h' = 2h)
    float b2v = lof(c_pr[BOFF + 1]);
    u64 acc = pk2(b2v, b2v);
#pragma unroll
    for (int j = 0; j < HH; j++) {
        acc = fma2(h0[j], c_pr[W2OFF + j], acc);
        acc = fma2(h1[j], c_pr[W2OFF + HH + j], acc);
    }
    float alo, ahi;
    upk2(acc, alo, ahi);
    out[base + tid] = alo;
    if (hasB) out[base + NTHR + tid] = ahi;
}

// ---------- light block: 128 elements, scalar ----------
__device__ __forceinline__ void run_light(
    const float* __restrict__ x, float* __restrict__ out, int B, int base,
    float* s_u, int tid)
{
    const int nb = min(NTHR, B - base);
    if (nb <= 0) return;
    phase1(x, base, nb * TT, s_u, false, tid);
    __syncthreads();

    if (tid >= nb) return;

    float h0[HH], c0[HH], h1[HH], c1[HH];
#pragma unroll
    for (int j = 0; j < HH; j++) { h0[j] = 0.f; c0[j] = 0.f; h1[j] = 0.f; c1[j] = 0.f; }

#pragma unroll 1
    for (int t = 0; t < TT; t++) {
        const float xin = s_u[tid * 15 + t];

        float hn[HH];
#pragma unroll
        for (int j = 0; j < HH; j++) {
            float z[4];
#pragma unroll
            for (int g = 0; g < 4; g++) {
                const int wb = L0OFF + j * 36 + 4 + g * 8;
                float zz = fmaf(xin, lof(c_pr[wb + 0]), lof(c_pr[L0OFF + j * 36 + g]));
                zz = fmaf(h0[0], lof(c_pr[wb + 1]), zz);
                zz = fmaf(h0[1], lof(c_pr[wb + 2]), zz);
                zz = fmaf(h0[2], lof(c_pr[wb + 3]), zz);
                zz = fmaf(h0[3], lof(c_pr[wb + 4]), zz);
                zz = fmaf(h0[4], lof(c_pr[wb + 5]), zz);
                zz = fmaf(h0[5], lof(c_pr[wb + 6]), zz);
                zz = fmaf(h0[6], lof(c_pr[wb + 7]), zz);
                z[g] = zz;
            }
            hn[j] = cell_update_s(z, c0[j]);
        }

        float hn1[HH];
#pragma unroll
        for (int j = 0; j < HH; j++) {
            float z[4];
#pragma unroll
            for (int g = 0; g < 4; g++) {
                const int rp = L1OFF + (g * HH + j) * 16;
                float zz = lof(c_pr[rp + 0]);
                zz = fmaf(hn[0], lof(c_pr[rp + 1]), zz);
                zz = fmaf(hn[1], lof(c_pr[rp + 2]), zz);
                zz = fmaf(hn[2], lof(c_pr[rp + 3]), zz);
                zz = fmaf(hn[3], lof(c_pr[rp + 4]), zz);
                zz = fmaf(hn[4], lof(c_pr[rp + 5]), zz);
                zz = fmaf(hn[5], lof(c_pr[rp + 6]), zz);
                zz = fmaf(hn[6], lof(c_pr[rp + 7]), zz);
                zz = fmaf(h1[0], lof(c_pr[rp + 8]), zz);
                zz = fmaf(h1[1], lof(c_pr[rp + 9]), zz);
                zz = fmaf(h1[2], lof(c_pr[rp + 10]), zz);
                zz = fmaf(h1[3], lof(c_pr[rp + 11]), zz);
                zz = fmaf(h1[4], lof(c_pr[rp + 12]), zz);
                zz = fmaf(h1[5], lof(c_pr[rp + 13]), zz);
                zz = fmaf(h1[6], lof(c_pr[rp + 14]), zz);
                z[g] = zz;
            }
            hn1[j] = cell_update_s(z, c1[j]);
        }

#pragma unroll
        for (int j = 0; j < HH; j++) { h0[j] = hn[j]; h1[j] = hn1[j]; }
    }

    float acc = lof(c_pr[BOFF + 1]);
#pragma unroll
    for (int j = 0; j < HH; j++) {
        acc = fmaf(h0[j], lof(c_pr[W2OFF + j]), acc);
        acc = fmaf(h1[j], lof(c_pr[W2OFF + HH + j]), acc);
    }
    out[base + tid] = acc;
}

__global__ __launch_bounds__(NTHR, 4)
void lstm_fused_kernel(const float* __restrict__ x,
                       float* __restrict__ out, int B, int nfull)
{
    __shared__ __align__(16) u64 s_up[NTHR * 15];
    const int tid = threadIdx.x;
    const int bid = blockIdx.x;
    if (bid < nfull) {
        run_packed(x, out, B, bid * (2 * NTHR), s_up, tid);
    } else {
        run_light(x, out, B, nfull * (2 * NTHR) + (bid - nfull) * NTHR,
                  (float*)s_up, tid);
    }
}

extern "C" void kernel_launch(void* const* d_in, const int* in_sizes, int n_in,
                              void* d_out, int out_size) {
    const float* x    = (const float*)d_in[0];
    const float* w1   = (const float*)d_in[1];
    const float* b1   = (const float*)d_in[2];
    const float* wih0 = (const float*)d_in[3];
    const float* whh0 = (const float*)d_in[4];
    const float* bih0 = (const float*)d_in[5];
    const float* bhh0 = (const float*)d_in[6];
    const float* wih1 = (const float*)d_in[7];
    const float* whh1 = (const float*)d_in[8];
    const float* bih1 = (const float*)d_in[9];
    const float* bhh1 = (const float*)d_in[10];
    const float* w2   = (const float*)d_in[11];
    const float* b2   = (const float*)d_in[12];
    float* out = (float*)d_out;

    const int B = out_size;                 // 262144

    prep_weights<<<1, 32>>>(w1, b1, wih0, whh0, bih0, bhh0,
                            wih1, whh1, bih1, bhh1, w2, b2);

    void* gp = nullptr;
    cudaGetSymbolAddress(&gp, g_prep);
    cudaMemcpyToSymbolAsync(c_pr, gp, WTOTAL * sizeof(u64), 0,
                            cudaMemcpyDeviceToDevice, 0);

    int sms = 148;
    cudaDeviceGetAttribute(&sms, cudaDevAttrMultiProcessorCount, 0);
    int grid   = 2 * 4 * sms;
    int chunks = (B + NTHR - 1) / NTHR;
    if (chunks > 2 * grid) grid = (chunks + 1) / 2;
    int nfull = chunks - grid;
    if (nfull < 0) nfull = 0;
    if (nfull > grid) nfull = grid;

    lstm_fused_kernel<<<grid, NTHR>>>(x, out, B, nfull);
}

// round 16
// speedup vs baseline: 1.3535x; 1.3535x over previous
#include <cuda_runtime.h>
#include <cstdint>

#define TT 14
#define HH 7
#define FF 12
#define NTHR 128

// constant-bank weight image: [l0 252][l1 448][w1 12][w2 14][blin,b2]
#define L0OFF 0
#define L1OFF 252
#define W1OFF 700
#define W2OFF 712
#define BOFF  726
#define WTOTAL 728

__device__                   float g_prep[WTOTAL];
__constant__ __align__(16)   float c_all[WTOTAL];

// ---------- hardware tanh (1 MUFU op) ----------
__device__ __forceinline__ float tanh_(float x) {
    float r;
    asm("tanh.approx.f32 %0, %1;" : "=f"(r) : "f"(x));
    return r;
}

// Gate-folded LSTM cell update (weights pre-scaled; h carried as h'=2h).
__device__ __forceinline__ float cell_update(const float z[4], float& c) {
    float ti = tanh_(z[0]);
    float tf = tanh_(z[1]);
    float tg = tanh_(z[2]);
    float to = tanh_(z[3]);
    float iv = fmaf(0.5f, ti, 0.5f);
    float fv = fmaf(0.5f, tf, 0.5f);
    float cv = fmaf(fv, c, iv * tg);
    c = cv;
    return (to + 1.0f) * tanh_(cv);   // = 2*h_true
}

// ---------- prep kernel: scale + layout weights into g_prep ----------
__global__ void prep_weights(
    const float* __restrict__ w1,  const float* __restrict__ b1,
    const float* __restrict__ wih0, const float* __restrict__ whh0,
    const float* __restrict__ bih0, const float* __restrict__ bhh0,
    const float* __restrict__ wih1, const float* __restrict__ whh1,
    const float* __restrict__ bih1, const float* __restrict__ bhh1,
    const float* __restrict__ w2,  const float* __restrict__ b2)
{
    int r = threadIdx.x;
    if (r < 28) {
        int g = r / 7, j = r % 7;
        const bool ifo = (g != 2);
        const float sb = ifo ? 0.5f : 1.0f;     // bias scale
        const float sx = ifo ? 0.5f : 1.0f;     // non-hidden-input weight scale
        const float sh = ifo ? 0.25f : 0.5f;    // hidden-input weight scale

        g_prep[L0OFF + j * 36 + g] = (bih0[r] + bhh0[r]) * sb;
        g_prep[L0OFF + j * 36 + 4 + g * 8 + 0] = wih0[r] * sx;
#pragma unroll
        for (int k = 0; k < 7; k++)
            g_prep[L0OFF + j * 36 + 4 + g * 8 + 1 + k] = whh0[r * 7 + k] * sh;

        g_prep[L1OFF + r * 16 + 0] = (bih1[r] + bhh1[r]) * sb;
#pragma unroll
        for (int k = 0; k < 7; k++)
            g_prep[L1OFF + r * 16 + 1 + k] = wih1[r * 7 + k] * sh;
#pragma unroll
        for (int k = 0; k < 7; k++)
            g_prep[L1OFF + r * 16 + 8 + k] = whh1[r * 7 + k] * sh;
        g_prep[L1OFF + r * 16 + 15] = 0.f;
    }
    if (r < FF)     g_prep[W1OFF + r] = w1[r];
    if (r < 2 * HH) g_prep[W2OFF + r] = w2[r] * 0.5f;   // undo h' = 2h
    if (r == 0) { g_prep[BOFF + 0] = b1[0]; g_prep[BOFF + 1] = b2[0]; }
}

// EB-templated block body: EB=1 compiles with NO second chain.
template <int EB>
__device__ __forceinline__ void run_block(
    const float* __restrict__ x, float* __restrict__ out, int B, int base,
    float* s_u, int tid)
{
    const int cap = EB * NTHR;
    const int nb = min(cap, B - base);   // block-uniform
    if (nb <= 0) return;
    const int cnt = nb * TT;

    // ---- phase 1: coalesced linear1 + tanh (vector constant loads) ----
    {
        const float blin = c_all[BOFF + 0];
        const float4* w14 = (const float4*)&c_all[W1OFF];
        float4 wA = w14[0], wB = w14[1], wC = w14[2];
        const int iters = (cnt + NTHR - 1) / NTHR;
        const float* xb = x + (long)base * TT * FF;
#pragma unroll 1
        for (int it = 0; it < iters; it++) {
            int idx = it * NTHR + tid;
            if (idx < cnt) {
                int bl = idx / TT;
                int t  = idx - bl * TT;
                const float4* px = (const float4*)(xb + (long)idx * FF);
                float4 a0 = px[0], a1 = px[1], a2 = px[2];
                float s = blin;
                s = fmaf(a0.x, wA.x, s); s = fmaf(a0.y, wA.y, s);
                s = fmaf(a0.z, wA.z, s); s = fmaf(a0.w, wA.w, s);
                s = fmaf(a1.x, wB.x, s); s = fmaf(a1.y, wB.y, s);
                s = fmaf(a1.z, wB.z, s); s = fmaf(a1.w, wB.w, s);
                s = fmaf(a2.x, wC.x, s); s = fmaf(a2.y, wC.y, s);
                s = fmaf(a2.z, wC.z, s); s = fmaf(a2.w, wC.w, s);
                s_u[bl * 15 + t] = tanh_(s);
            }
        }
    }
    __syncthreads();

    if (tid >= nb) return;

    int ur[EB];
#pragma unroll
    for (int e = 0; e < EB; e++) ur[e] = min(e * NTHR + tid, nb - 1);

    float h0[EB][HH], c0[EB][HH], h1[EB][HH], c1[EB][HH];
#pragma unroll
    for (int e = 0; e < EB; e++)
#pragma unroll
        for (int j = 0; j < HH; j++) {
            h0[e][j] = 0.f; c0[e][j] = 0.f; h1[e][j] = 0.f; c1[e][j] = 0.f;
        }

#pragma unroll 1
    for (int t = 0; t < TT; t++) {
        float xin[EB];
#pragma unroll
        for (int e = 0; e < EB; e++) xin[e] = s_u[ur[e] * 15 + t];

        // ---- layer 0: per j, record = 9 x float4 [biases | 4 x (wih, whh0..6)]
        float hn[EB][HH];
#pragma unroll
        for (int j = 0; j < HH; j++) {
            const float4* rec4 = (const float4*)&c_all[L0OFF + j * 36];
            float4 bz = rec4[0];
            const float bsel[4] = {bz.x, bz.y, bz.z, bz.w};
            float z[EB][4];
#pragma unroll
            for (int g = 0; g < 4; g++) {
                float4 r0 = rec4[1 + g * 2];
                float4 r1 = rec4[2 + g * 2];
#pragma unroll
                for (int e = 0; e < EB; e++) {
                    float zz = fmaf(xin[e], r0.x, bsel[g]);
                    zz = fmaf(h0[e][0], r0.y, zz);
                    zz = fmaf(h0[e][1], r0.z, zz);
                    zz = fmaf(h0[e][2], r0.w, zz);
                    zz = fmaf(h0[e][3], r1.x, zz);
                    zz = fmaf(h0[e][4], r1.y, zz);
                    zz = fmaf(h0[e][5], r1.z, zz);
                    zz = fmaf(h0[e][6], r1.w, zz);
                    z[e][g] = zz;
                }
            }
#pragma unroll
            for (int e = 0; e < EB; e++)
                hn[e][j] = cell_update(z[e], c0[e][j]);
        }

        // ---- layer 1: row r = 4 x float4 [b, wih0..6, whh0..6, pad]
        float hn1[EB][HH];
#pragma unroll
        for (int j = 0; j < HH; j++) {
            float z[EB][4];
#pragma unroll
            for (int g = 0; g < 4; g++) {
                const float4* rp4 = (const float4*)&c_all[L1OFF + (g * HH + j) * 16];
                float4 r0 = rp4[0];
                float4 r1 = rp4[1];
                float4 r2 = rp4[2];
                float4 r3 = rp4[3];
#pragma unroll
                for (int e = 0; e < EB; e++) {
                    float zz = r0.x;
                    zz = fmaf(hn[e][0], r0.y, zz);
                    zz = fmaf(hn[e][1], r0.z, zz);
                    zz = fmaf(hn[e][2], r0.w, zz);
                    zz = fmaf(hn[e][3], r1.x, zz);
                    zz = fmaf(hn[e][4], r1.y, zz);
                    zz = fmaf(hn[e][5], r1.z, zz);
                    zz = fmaf(hn[e][6], r1.w, zz);
                    zz = fmaf(h1[e][0], r2.x, zz);
                    zz = fmaf(h1[e][1], r2.y, zz);
                    zz = fmaf(h1[e][2], r2.z, zz);
                    zz = fmaf(h1[e][3], r2.w, zz);
                    zz = fmaf(h1[e][4], r3.x, zz);
                    zz = fmaf(h1[e][5], r3.y, zz);
                    zz = fmaf(h1[e][6], r3.z, zz);
                    z[e][g] = zz;
                }
            }
#pragma unroll
            for (int e = 0; e < EB; e++)
                hn1[e][j] = cell_update(z[e], c1[e][j]);
        }

#pragma unroll
        for (int e = 0; e < EB; e++)
#pragma unroll
            for (int j = 0; j < HH; j++) {
                h0[e][j] = hn[e][j]; h1[e][j] = hn1[e][j];
            }
    }

    // ---- phase 3 ----
#pragma unroll
    for (int e = 0; e < EB; e++) {
        float acc = c_all[BOFF + 1];
#pragma unroll
        for (int j = 0; j < HH; j++) {
            acc = fmaf(h0[e][j], c_all[W2OFF + j], acc);
            acc = fmaf(h1[e][j], c_all[W2OFF + HH + j], acc);
        }
        int gb = base + e * NTHR + tid;
        if (gb < B) out[gb] = acc;
    }
}

__global__ __launch_bounds__(NTHR, 4)
void lstm_fused_kernel(const float* __restrict__ x,
                       float* __restrict__ out, int B, int nfull)
{
    __shared__ float s_u[2 * NTHR * 15];
    const int tid = threadIdx.x;
    const int bid = blockIdx.x;
    if (bid < nfull) {
        run_block<2>(x, out, B, bid * (2 * NTHR), s_u, tid);
    } else {
        run_block<1>(x, out, B, nfull * (2 * NTHR) + (bid - nfull) * NTHR,
                     s_u, tid);
    }
}

extern "C" void kernel_launch(void* const* d_in, const int* in_sizes, int n_in,
                              void* d_out, int out_size) {
    const float* x    = (const float*)d_in[0];
    const float* w1   = (const float*)d_in[1];
    const float* b1   = (const float*)d_in[2];
    const float* wih0 = (const float*)d_in[3];
    const float* whh0 = (const float*)d_in[4];
    const float* bih0 = (const float*)d_in[5];
    const float* bhh0 = (const float*)d_in[6];
    const float* wih1 = (const float*)d_in[7];
    const float* whh1 = (const float*)d_in[8];
    const float* bih1 = (const float*)d_in[9];
    const float* bhh1 = (const float*)d_in[10];
    const float* w2   = (const float*)d_in[11];
    const float* b2   = (const float*)d_in[12];
    float* out = (float*)d_out;

    const int B = out_size;                 // 262144

    // 1) scale + layout weights into a __device__ buffer
    prep_weights<<<1, 32>>>(w1, b1, wih0, whh0, bih0, bhh0,
                            wih1, whh1, bih1, bhh1, w2, b2);

    // 2) copy into the constant bank (D2D memcpy node; graph-capturable)
    void* gp = nullptr;
    cudaGetSymbolAddress(&gp, g_prep);
    cudaMemcpyToSymbolAsync(c_all, gp, WTOTAL * sizeof(float), 0,
                            cudaMemcpyDeviceToDevice, 0);

    // 3) main kernel: exact 2 waves @ 4/SM, heterogeneous EB2/EB1 fill
    int sms = 148;
    cudaDeviceGetAttribute(&sms, cudaDevAttrMultiProcessorCount, 0);
    int grid   = 2 * 4 * sms;
    int chunks = (B + NTHR - 1) / NTHR;
    if (chunks > 2 * grid) grid = (chunks + 1) / 2;
    int nfull = chunks - grid;
    if (nfull < 0) nfull = 0;
    if (nfull > grid) nfull = grid;

    lstm_fused_kernel<<<grid, NTHR>>>(x, out, B, nfull);
}